// round 4
// baseline (speedup 1.0000x reference)
#include <cuda_runtime.h>
#include <cuda_bf16.h>

// PathBasedLoss: mean over B rows of (group[argmax(pred[b,:8])] != group[target[b]])
// groups: classes 0-2 -> 0, 3-5 -> 1, 6-7 -> 2
// predictions: float32 [B, 8], targets: int32 [B], output: float32 scalar.
//
// Single fused kernel; self-wrapping ticket (atomicInc mod gridDim) makes it
// graph-replay safe with no init kernel. Group-of-argmax computed via three
// group maxes + ordered >= compares (preserves first-index tie-break).

#define PBL_THREADS 256
#define PBL_ROWS 16
#define PBL_CHUNK (PBL_THREADS * PBL_ROWS)   // 4096 rows per block
#define PBL_MAX_BLOCKS 8192

static __device__ unsigned int g_partials[PBL_MAX_BLOCKS];
static __device__ unsigned int g_ticket;  // zero-init; self-wraps each launch

// 2-bit group LUT for classes 0..7: 0,0,0,1,1,1,2,2 packed little-endian
#define PBL_GROUP_LUT 0xA540u

template <bool GUARD>
__global__ void __launch_bounds__(PBL_THREADS) pbl_fused_kernel(
    const float4* __restrict__ preds,   // 2 float4 per row
    const int* __restrict__ targets,    // int32 targets
    float* __restrict__ out,
    int batch, float inv_batch)
{
    const int base = blockIdx.x * PBL_CHUNK + threadIdx.x;

    unsigned int local = 0;
    #pragma unroll
    for (int i = 0; i < PBL_ROWS; i++) {
        int r = base + i * PBL_THREADS;
        if (!GUARD || r < batch) {
            float4 a = preds[2 * r];
            float4 b = preds[2 * r + 1];
            int t = targets[r];

            // group maxes (independent trees -> short critical path)
            float m0 = fmaxf(fmaxf(a.x, a.y), a.z);   // classes 0..2
            float m1 = fmaxf(fmaxf(a.w, b.x), b.y);   // classes 3..5
            float m2 = fmaxf(b.z, b.w);               // classes 6..7

            // group of argmax; >= ordering == first-index tie-break at group level
            int pg = (m0 >= m1 && m0 >= m2) ? 0 : ((m1 >= m2) ? 1 : 2);
            int tg = (int)((PBL_GROUP_LUT >> (t << 1)) & 3u);

            local += (unsigned int)(pg != tg);
        }
    }

    // intra-warp reduce
    #pragma unroll
    for (int off = 16; off > 0; off >>= 1)
        local += __shfl_down_sync(0xffffffffu, local, off);

    __shared__ unsigned int warp_sums[PBL_THREADS / 32];
    __shared__ bool is_last;
    int lane = threadIdx.x & 31;
    int wid = threadIdx.x >> 5;
    if (lane == 0) warp_sums[wid] = local;
    __syncthreads();

    if (threadIdx.x == 0) {
        unsigned int blk = 0;
        #pragma unroll
        for (int w = 0; w < PBL_THREADS / 32; w++) blk += warp_sums[w];
        g_partials[blockIdx.x] = blk;
        __threadfence();
        unsigned int old = atomicInc(&g_ticket, gridDim.x - 1);  // wraps to 0
        is_last = (old == gridDim.x - 1);
    }
    __syncthreads();

    if (is_last) {
        unsigned int sum = 0;
        for (int i = threadIdx.x; i < (int)gridDim.x; i += PBL_THREADS)
            sum += g_partials[i];
        #pragma unroll
        for (int off = 16; off > 0; off >>= 1)
            sum += __shfl_down_sync(0xffffffffu, sum, off);
        if (lane == 0) warp_sums[wid] = sum;
        __syncthreads();
        if (threadIdx.x == 0) {
            unsigned int total = 0;
            #pragma unroll
            for (int w = 0; w < PBL_THREADS / 32; w++) total += warp_sums[w];
            out[0] = (float)total * inv_batch;
        }
    }
}

extern "C" void kernel_launch(void* const* d_in, const int* in_sizes, int n_in,
                              void* d_out, int out_size) {
    const float4* preds = (const float4*)d_in[0];
    const int* targets = (const int*)d_in[1];
    float* out = (float*)d_out;

    int batch = in_sizes[1];  // targets element count = B
    float inv_batch = 1.0f / (float)batch;

    if (batch % PBL_CHUNK == 0) {
        int blocks = batch / PBL_CHUNK;
        if (blocks <= PBL_MAX_BLOCKS) {
            pbl_fused_kernel<false><<<blocks, PBL_THREADS>>>(preds, targets, out,
                                                             batch, inv_batch);
            return;
        }
    }
    int blocks = (batch + PBL_CHUNK - 1) / PBL_CHUNK;
    if (blocks > PBL_MAX_BLOCKS) blocks = PBL_MAX_BLOCKS;  // (not hit for B=4M)
    pbl_fused_kernel<true><<<blocks, PBL_THREADS>>>(preds, targets, out,
                                                    batch, inv_batch);
}

// round 5
// speedup vs baseline: 1.1604x; 1.1604x over previous
#include <cuda_runtime.h>
#include <cuda_bf16.h>

// PathBasedLoss: mean over B rows of (group[argmax(pred[b,:8])] != group[target[b]])
// groups: classes 0-2 -> 0, 3-5 -> 1, 6-7 -> 2
// predictions: float32 [B, 8], targets: int32 [B], output: float32 scalar.
//
// Single fused kernel. Per-block count via one atomicAdd into a global counter;
// self-wrapping ticket (atomicInc mod gridDim) elects the last block, which
// reads+resets the counter with atomicExch -> graph-replay safe, no init kernel.

#define PBL_THREADS 256
#define PBL_ROWS 8
#define PBL_CHUNK (PBL_THREADS * PBL_ROWS)   // 2048 rows per block

static __device__ unsigned int g_count;   // zero-init; reset by last block each launch
static __device__ unsigned int g_ticket;  // zero-init; self-wraps each launch

// 2-bit group LUT for classes 0..7: 0,0,0,1,1,1,2,2 packed little-endian
#define PBL_GROUP_LUT 0xA540u

template <bool GUARD>
__global__ void __launch_bounds__(PBL_THREADS) pbl_fused_kernel(
    const float4* __restrict__ preds,   // 2 float4 per row
    const int* __restrict__ targets,    // int32 targets
    float* __restrict__ out,
    int batch, float inv_batch)
{
    const int base = blockIdx.x * PBL_CHUNK + threadIdx.x;

    unsigned int local = 0;
    #pragma unroll
    for (int i = 0; i < PBL_ROWS; i++) {
        int r = base + i * PBL_THREADS;
        if (!GUARD || r < batch) {
            float4 a = preds[2 * r];
            float4 b = preds[2 * r + 1];
            int t = targets[r];

            // group maxes (independent trees -> short critical path)
            float m0 = fmaxf(fmaxf(a.x, a.y), a.z);   // classes 0..2
            float m1 = fmaxf(fmaxf(a.w, b.x), b.y);   // classes 3..5
            float m2 = fmaxf(b.z, b.w);               // classes 6..7

            // group of argmax; >= ordering == first-index tie-break at group level
            int pg = (m0 >= m1 && m0 >= m2) ? 0 : ((m1 >= m2) ? 1 : 2);
            int tg = (int)((PBL_GROUP_LUT >> (t << 1)) & 3u);

            local += (unsigned int)(pg != tg);
        }
    }

    // intra-warp reduce
    #pragma unroll
    for (int off = 16; off > 0; off >>= 1)
        local += __shfl_down_sync(0xffffffffu, local, off);

    __shared__ unsigned int warp_sums[PBL_THREADS / 32];
    __shared__ bool is_last;
    int lane = threadIdx.x & 31;
    int wid = threadIdx.x >> 5;
    if (lane == 0) warp_sums[wid] = local;
    __syncthreads();

    if (threadIdx.x == 0) {
        unsigned int blk = 0;
        #pragma unroll
        for (int w = 0; w < PBL_THREADS / 32; w++) blk += warp_sums[w];
        atomicAdd(&g_count, blk);
        __threadfence();
        unsigned int old = atomicInc(&g_ticket, gridDim.x - 1);  // wraps to 0
        is_last = (old == gridDim.x - 1);
    }
    __syncthreads();

    if (is_last && threadIdx.x == 0) {
        // all blocks' adds are ordered before their ticket increment; seeing the
        // final ticket value implies all adds are visible. Read + reset in one op.
        unsigned int total = atomicExch(&g_count, 0u);
        out[0] = (float)total * inv_batch;
    }
}

extern "C" void kernel_launch(void* const* d_in, const int* in_sizes, int n_in,
                              void* d_out, int out_size) {
    const float4* preds = (const float4*)d_in[0];
    const int* targets = (const int*)d_in[1];
    float* out = (float*)d_out;

    int batch = in_sizes[1];  // targets element count = B
    float inv_batch = 1.0f / (float)batch;

    if (batch % PBL_CHUNK == 0) {
        int blocks = batch / PBL_CHUNK;  // B=4M -> 2048 blocks
        pbl_fused_kernel<false><<<blocks, PBL_THREADS>>>(preds, targets, out,
                                                         batch, inv_batch);
    } else {
        int blocks = (batch + PBL_CHUNK - 1) / PBL_CHUNK;
        pbl_fused_kernel<true><<<blocks, PBL_THREADS>>>(preds, targets, out,
                                                        batch, inv_batch);
    }
}